// round 17
// baseline (speedup 1.0000x reference)
#include <cuda_runtime.h>

// LIF constant-current encoder — closed form, de-interleaved streams with
// asymmetric chunking. x: [N] fp32 (N = 512*512).
// out: voltages [128*N] then spikes [128*N], fp32.
// v_t = x(1 - 0.9^t) between resets; strict threshold (v - 1 > 0) and
// v_t < x mean x <= 1 never spikes: trajectory closed-form, z == 0.
// grid.y in [0,64): voltage CTA, 2-step chunk (compute-carrying stream).
// grid.y in [64,80): spike CTA, 8-step chunk (pure zero-fill — amortize the
// per-CTA x load / branch over 4x more stores). Each CTA writes one
// contiguous region. x > 1 (absent here) falls back to exact replay.

#define SEQ_LENGTH 128
#define CHUNK_V    2
#define CHUNK_Z    8
#define NCHUNKS_V  (SEQ_LENGTH / CHUNK_V)   // 64
#define NCHUNKS_Z  (SEQ_LENGTH / CHUNK_Z)   // 16
#define ALPHA      0.1f
#define DECAY      0.9f
#define LOG2_DECAY (-0.15200309344504997f)  // log2(0.9)
#define V_TH       1.0f
#define BLOCK      128

__device__ __forceinline__ void lif_step(float4& v, const float4& xv, float4& z) {
    v.x = fmaf(ALPHA, xv.x - v.x, v.x);
    v.y = fmaf(ALPHA, xv.y - v.y, v.y);
    v.z = fmaf(ALPHA, xv.z - v.z, v.z);
    v.w = fmaf(ALPHA, xv.w - v.w, v.w);
    z.x = (v.x > V_TH) ? 1.f : 0.f;
    z.y = (v.y > V_TH) ? 1.f : 0.f;
    z.z = (v.z > V_TH) ? 1.f : 0.f;
    z.w = (v.w > V_TH) ? 1.f : 0.f;
    v.x = (z.x != 0.f) ? 0.f : v.x;
    v.y = (z.y != 0.f) ? 0.f : v.y;
    v.z = (z.z != 0.f) ? 0.f : v.z;
    v.w = (z.w != 0.f) ? 0.f : v.w;
}

__global__ __launch_bounds__(BLOCK)
void lif_encoder_kernel(const float* __restrict__ x,
                        float* __restrict__ out,
                        int n4 /* N/4 */, int n /* N */) {
    int i = blockIdx.x * blockDim.x + threadIdx.x;
    if (i >= n4) return;

    const int role = (blockIdx.y >= NCHUNKS_V) ? 1 : 0;  // 0 = voltages, 1 = spikes
    const float4 xv = reinterpret_cast<const float4*>(x)[i];
    const float xmax = fmaxf(fmaxf(xv.x, xv.y), fmaxf(xv.z, xv.w));

    if (role == 0) {
        const int t0 = blockIdx.y * CHUNK_V;
        float4* vp = reinterpret_cast<float4*>(out) + (size_t)t0 * n4 + i;

        if (xmax <= 1.0f) {
            // Voltage stream: v_t = x * (1 - 0.9^(t+1)).
            float p = exp2f((float)(t0 + 1) * LOG2_DECAY);   // 0.9^(t0+1)
            #pragma unroll
            for (int t = 0; t < CHUNK_V; ++t) {
                float4 v;
                v.x = fmaf(-p, xv.x, xv.x);
                v.y = fmaf(-p, xv.y, xv.y);
                v.z = fmaf(-p, xv.z, xv.z);
                v.w = fmaf(-p, xv.w, xv.w);
                __stcs(vp, v);
                p *= DECAY;
                vp += n4;
            }
        } else {
            float4 v = make_float4(0.f, 0.f, 0.f, 0.f);
            float4 z;
            #pragma unroll 1
            for (int s = 0; s < t0; ++s)
                lif_step(v, xv, z);
            #pragma unroll
            for (int t = 0; t < CHUNK_V; ++t) {
                lif_step(v, xv, z);
                __stcs(vp, v);
                vp += n4;
            }
        }
    } else {
        const int t0 = (blockIdx.y - NCHUNKS_V) * CHUNK_Z;
        float4* zp = reinterpret_cast<float4*>(out + (size_t)SEQ_LENGTH * n)
                     + (size_t)t0 * n4 + i;

        if (xmax <= 1.0f) {
            // Spike stream: all zeros (no spikes for x <= 1).
            const float4 zero = make_float4(0.f, 0.f, 0.f, 0.f);
            #pragma unroll
            for (int t = 0; t < CHUNK_Z; ++t) {
                __stcs(zp, zero);
                zp += n4;
            }
        } else {
            float4 v = make_float4(0.f, 0.f, 0.f, 0.f);
            float4 z;
            #pragma unroll 1
            for (int s = 0; s < t0; ++s)
                lif_step(v, xv, z);
            #pragma unroll
            for (int t = 0; t < CHUNK_Z; ++t) {
                lif_step(v, xv, z);
                __stcs(zp, z);
                zp += n4;
            }
        }
    }
}

extern "C" void kernel_launch(void* const* d_in, const int* in_sizes, int n_in,
                              void* d_out, int out_size) {
    const float* x = (const float*)d_in[0];
    float* out = (float*)d_out;
    int n = in_sizes[0];       // 262144
    int n4 = n / 4;            // 65536

    dim3 block(BLOCK);
    dim3 grid((n4 + BLOCK - 1) / BLOCK, NCHUNKS_V + NCHUNKS_Z);  // 64 + 16
    lif_encoder_kernel<<<grid, block>>>(x, out, n4, n);
}